// round 1
// baseline (speedup 1.0000x reference)
#include <cuda_runtime.h>

// Chebyshev-KAN: out[b] = sum_d sum_{k=0..8} coeff[d*9+k] * T_k(x[b,d])
// x: (16384, 512) f32 row-major; coeff: (4608,) f32; out: (16384,) f32.
// HBM-bound (33.6 MB read). Strategy: coalesced float4 reads of x,
// coeffs staged in smem, FMA recurrence, warp-shuffle reduction.

#define BATCH      16384
#define DIM        512
#define NDEG       9          // degree 8 -> 9 terms
#define NCOEF      (DIM * NDEG)   // 4608
#define ROWS_PER_BLOCK 4
#define THREADS    512        // 128 threads per row, 4 dims (float4) per thread

__global__ __launch_bounds__(THREADS)
void kan_cheb_kernel(const float* __restrict__ x,
                     const float* __restrict__ coeff,
                     float* __restrict__ out)
{
    __shared__ float s_coef[NCOEF];          // 18432 B
    __shared__ float s_part[THREADS / 32];   // 16 warp partials

    const int tid = threadIdx.x;

    // Stage coefficients into smem (vectorized: 4608/4 = 1152 float4)
    {
        const float4* c4 = reinterpret_cast<const float4*>(coeff);
        float4* s4 = reinterpret_cast<float4*>(s_coef);
        #pragma unroll
        for (int i = tid; i < NCOEF / 4; i += THREADS)
            s4[i] = c4[i];
    }
    __syncthreads();

    const int row_in_blk = tid >> 7;            // /128
    const int lane128    = tid & 127;           // thread within row
    const int row        = blockIdx.x * ROWS_PER_BLOCK + row_in_blk;
    const int dim0       = lane128 * 4;         // 4 consecutive dims per thread

    // Coalesced float4 load: 128 consecutive threads -> 2 KB contiguous
    const float4 xv = reinterpret_cast<const float4*>(x + (size_t)row * DIM)[lane128];

    float acc = 0.0f;
    const float xs[4] = {xv.x, xv.y, xv.z, xv.w};
    #pragma unroll
    for (int j = 0; j < 4; ++j) {
        const float* c = &s_coef[(dim0 + j) * NDEG];
        const float xx = xs[j];
        const float x2 = xx + xx;
        float tp = 1.0f;            // T0
        float t  = xx;              // T1
        float a  = fmaf(c[1], xx, c[0]);
        #pragma unroll
        for (int k = 2; k < NDEG; ++k) {
            float tn = fmaf(x2, t, -tp);
            a = fmaf(c[k], tn, a);
            tp = t; t = tn;
        }
        acc += a;
    }

    // Warp reduction (4 warps per row; warps never straddle rows)
    #pragma unroll
    for (int off = 16; off > 0; off >>= 1)
        acc += __shfl_xor_sync(0xffffffffu, acc, off);

    const int warp_id = tid >> 5;               // 0..15
    if ((tid & 31) == 0) s_part[warp_id] = acc;
    __syncthreads();

    // One thread per row sums its 4 warp partials
    if (tid < ROWS_PER_BLOCK) {
        const int base = tid * 4;
        float r = s_part[base] + s_part[base + 1] + s_part[base + 2] + s_part[base + 3];
        out[blockIdx.x * ROWS_PER_BLOCK + tid] = r;
    }
}

extern "C" void kernel_launch(void* const* d_in, const int* in_sizes, int n_in,
                              void* d_out, int out_size)
{
    const float* x     = (const float*)d_in[0];
    const float* coeff = (const float*)d_in[1];
    // d_in[2] = degree (int32, always 8) — compile-time constant here.
    float* out = (float*)d_out;

    kan_cheb_kernel<<<BATCH / ROWS_PER_BLOCK, THREADS>>>(x, coeff, out);
}

// round 2
// speedup vs baseline: 1.9587x; 1.9587x over previous
#include <cuda_runtime.h>

// Chebyshev-KAN: out[b] = sum_d sum_{k=0..8} coeff[d*9+k] * T_k(x[b,d])
// x: (16384, 512) f32; coeff: (4608,) f32; out: (16384,) f32.
//
// R2 design: coefficients converted to monomial basis and held in REGISTERS
// (packed f32x2 pairs). No per-row coefficient loads at all. Packed Horner
// (fma.rn.f32x2) evaluates two dims per instruction. Warp = 128 dims (4 dims
// per lane), 4 warps per row, 8 warps per block -> 2 rows in flight with
// one-iteration prefetch for memory-level parallelism.

#define BATCH          16384
#define DIM            512
#define NDEG           9
#define THREADS        256
#define ROWS_PER_BLOCK 16
#define NITER          (ROWS_PER_BLOCK / 4)   // 4 rows per iteration
#define GRID           (BATCH / ROWS_PER_BLOCK)  // 1024

typedef unsigned long long ull;

__device__ __forceinline__ ull pack2(float lo, float hi) {
    ull r;
    asm("mov.b64 %0, {%1, %2};" : "=l"(r) : "f"(lo), "f"(hi));
    return r;
}
__device__ __forceinline__ void unpack2(ull v, float& lo, float& hi) {
    asm("mov.b64 {%0, %1}, %2;" : "=f"(lo), "=f"(hi) : "l"(v));
}
__device__ __forceinline__ ull fma2(ull a, ull b, ull c) {
    ull r;
    asm("fma.rn.f32x2 %0, %1, %2, %3;" : "=l"(r) : "l"(a), "l"(b), "l"(c));
    return r;
}
__device__ __forceinline__ ull add2(ull a, ull b) {
    ull r;
    asm("add.rn.f32x2 %0, %1, %2;" : "=l"(r) : "l"(a), "l"(b));
    return r;
}

// Chebyshev coefficients c[0..8] -> monomial coefficients a[0..8].
// T2=2x^2-1, T3=4x^3-3x, T4=8x^4-8x^2+1, T5=16x^5-20x^3+5x,
// T6=32x^6-48x^4+18x^2-1, T7=64x^7-112x^5+56x^3-7x,
// T8=128x^8-256x^6+160x^4-32x^2+1.
__device__ __forceinline__ void cheb2mono(const float* __restrict__ c, float* a) {
    a[8] = 128.0f * c[8];
    a[7] =  64.0f * c[7];
    a[6] = fmaf(-256.0f, c[8], 32.0f * c[6]);
    a[5] = fmaf(-112.0f, c[7], 16.0f * c[5]);
    a[4] = fmaf(160.0f, c[8], fmaf(-48.0f, c[6], 8.0f * c[4]));
    a[3] = fmaf( 56.0f, c[7], fmaf(-20.0f, c[5], 4.0f * c[3]));
    a[2] = fmaf(-32.0f, c[8], fmaf(18.0f, c[6], fmaf(-8.0f, c[4], 2.0f * c[2])));
    a[1] = fmaf( -7.0f, c[7], fmaf( 5.0f, c[5], fmaf(-3.0f, c[3], c[1])));
    a[0] = ((c[0] - c[2]) + (c[4] - c[6])) + c[8];
}

// Evaluate 4 dims (two packed Horner chains) and return their sum.
__device__ __forceinline__ float eval4(float4 xv, const ull* A, const ull* B) {
    ull xA = pack2(xv.x, xv.y);
    ull xB = pack2(xv.z, xv.w);
    ull p = A[8], q = B[8];
    #pragma unroll
    for (int k = 7; k >= 0; --k) {
        p = fma2(p, xA, A[k]);
        q = fma2(q, xB, B[k]);
    }
    ull s = add2(p, q);
    float lo, hi;
    unpack2(s, lo, hi);
    return lo + hi;
}

__global__ __launch_bounds__(THREADS, 3)
void kan_cheb_kernel(const float* __restrict__ x,
                     const float* __restrict__ coeff,
                     float* __restrict__ out)
{
    __shared__ __align__(16) float s_part[4][4];   // [row-in-iter][dim-group]

    const int tid  = threadIdx.x;
    const int lane = tid & 31;
    const int warp = tid >> 5;
    const int g    = warp & 3;      // dim group (0..3) -> dims [g*128, g*128+128)
    const int r    = warp >> 1 >> 1; // warp >> 2: row selector 0/1
    const int d0   = g * 128 + lane * 4;

    // ---- one-time: load 36 coeffs (9 x LDG.128), convert, pack ----
    float cf[36];
    {
        const float4* c4 = reinterpret_cast<const float4*>(coeff + d0 * NDEG);
        #pragma unroll
        for (int i = 0; i < 9; ++i) {
            float4 v = c4[i];
            cf[4 * i + 0] = v.x; cf[4 * i + 1] = v.y;
            cf[4 * i + 2] = v.z; cf[4 * i + 3] = v.w;
        }
    }
    ull A[9], B[9];
    {
        float t0[9], t1[9];
        cheb2mono(cf + 0,  t0);
        cheb2mono(cf + 9,  t1);
        #pragma unroll
        for (int k = 0; k < 9; ++k) A[k] = pack2(t0[k], t1[k]);
        cheb2mono(cf + 18, t0);
        cheb2mono(cf + 27, t1);
        #pragma unroll
        for (int k = 0; k < 9; ++k) B[k] = pack2(t0[k], t1[k]);
    }

    const int rowbase = blockIdx.x * ROWS_PER_BLOCK;
    const float4* xrow = reinterpret_cast<const float4*>(x);
    const int col4 = d0 >> 2;   // float4 column within a row (row = 128 float4)

    // prefetch iteration 0 (2 rows per warp)
    int prow = rowbase + 2 * r;
    float4 xa = xrow[(size_t)prow * 128 + col4];
    float4 xb = xrow[(size_t)(prow + 1) * 128 + col4];

    #pragma unroll
    for (int it = 0; it < NITER; ++it) {
        float4 cxa = xa, cxb = xb;
        if (it + 1 < NITER) {
            int nr = rowbase + (it + 1) * 4 + 2 * r;
            xa = xrow[(size_t)nr * 128 + col4];
            xb = xrow[(size_t)(nr + 1) * 128 + col4];
        }

        float acc0 = eval4(cxa, A, B);
        float acc1 = eval4(cxb, A, B);

        #pragma unroll
        for (int off = 16; off; off >>= 1) {
            acc0 += __shfl_xor_sync(0xffffffffu, acc0, off);
            acc1 += __shfl_xor_sync(0xffffffffu, acc1, off);
        }
        if (lane == 0) {
            s_part[2 * r + 0][g] = acc0;
            s_part[2 * r + 1][g] = acc1;
        }
        __syncthreads();
        if (tid < 4) {
            float4 v = *reinterpret_cast<const float4*>(s_part[tid]);
            out[rowbase + it * 4 + tid] = (v.x + v.y) + (v.z + v.w);
        }
        __syncthreads();
    }
}

extern "C" void kernel_launch(void* const* d_in, const int* in_sizes, int n_in,
                              void* d_out, int out_size)
{
    const float* x     = (const float*)d_in[0];
    const float* coeff = (const float*)d_in[1];
    // d_in[2] = degree (int32, fixed at 8) — baked in at compile time.
    float* out = (float*)d_out;

    kan_cheb_kernel<<<GRID, THREADS>>>(x, coeff, out);
}

// round 3
// speedup vs baseline: 1.9821x; 1.0119x over previous
#include <cuda_runtime.h>

// Chebyshev-KAN: out[b] = sum_d sum_{k=0..8} coeff[d*9+k] * T_k(x[b,d])
// x: (16384, 512) f32; coeff: (4608,) f32; out: (16384,) f32.
//
// R3: memory-latency-limited fix. Each block = 8 rows, 128 threads (4 warps).
// Warp g owns dims [g*128, g*128+128); each lane owns 4 dims, with monomial-
// converted coefficients held in registers as packed f32x2. All 8 row-loads
// (LDG.128) are front-batched per thread -> MLP=8 per warp (4KB in flight),
// 3x the per-SM bandwidth needed to hit the chip LTS cap. Single
// __syncthreads per block.

#define BATCH          16384
#define DIM            512
#define NDEG           9
#define THREADS        128
#define ROWS_PER_BLOCK 8
#define GRID           (BATCH / ROWS_PER_BLOCK)   // 2048

typedef unsigned long long ull;

__device__ __forceinline__ ull pack2(float lo, float hi) {
    ull r;
    asm("mov.b64 %0, {%1, %2};" : "=l"(r) : "f"(lo), "f"(hi));
    return r;
}
__device__ __forceinline__ void unpack2(ull v, float& lo, float& hi) {
    asm("mov.b64 {%0, %1}, %2;" : "=f"(lo), "=f"(hi) : "l"(v));
}
__device__ __forceinline__ ull fma2(ull a, ull b, ull c) {
    ull r;
    asm("fma.rn.f32x2 %0, %1, %2, %3;" : "=l"(r) : "l"(a), "l"(b), "l"(c));
    return r;
}
__device__ __forceinline__ ull add2(ull a, ull b) {
    ull r;
    asm("add.rn.f32x2 %0, %1, %2;" : "=l"(r) : "l"(a), "l"(b));
    return r;
}

// Chebyshev coeffs c[0..8] -> monomial coeffs a[0..8].
__device__ __forceinline__ void cheb2mono(const float* __restrict__ c, float* a) {
    a[8] = 128.0f * c[8];
    a[7] =  64.0f * c[7];
    a[6] = fmaf(-256.0f, c[8], 32.0f * c[6]);
    a[5] = fmaf(-112.0f, c[7], 16.0f * c[5]);
    a[4] = fmaf(160.0f, c[8], fmaf(-48.0f, c[6], 8.0f * c[4]));
    a[3] = fmaf( 56.0f, c[7], fmaf(-20.0f, c[5], 4.0f * c[3]));
    a[2] = fmaf(-32.0f, c[8], fmaf(18.0f, c[6], fmaf(-8.0f, c[4], 2.0f * c[2])));
    a[1] = fmaf( -7.0f, c[7], fmaf( 5.0f, c[5], fmaf(-3.0f, c[3], c[1])));
    a[0] = ((c[0] - c[2]) + (c[4] - c[6])) + c[8];
}

// Evaluate 4 dims (two packed Horner chains), return their sum.
__device__ __forceinline__ float eval4(float4 xv, const ull* A, const ull* B) {
    ull xA = pack2(xv.x, xv.y);
    ull xB = pack2(xv.z, xv.w);
    ull p = A[8], q = B[8];
    #pragma unroll
    for (int k = 7; k >= 0; --k) {
        p = fma2(p, xA, A[k]);
        q = fma2(q, xB, B[k]);
    }
    ull s = add2(p, q);
    float lo, hi;
    unpack2(s, lo, hi);
    return lo + hi;
}

__global__ __launch_bounds__(THREADS, 5)
void kan_cheb_kernel(const float* __restrict__ x,
                     const float* __restrict__ coeff,
                     float* __restrict__ out)
{
    __shared__ __align__(16) float s_part[ROWS_PER_BLOCK][4];  // [row][group]

    const int tid  = threadIdx.x;
    const int lane = tid & 31;
    const int g    = tid >> 5;            // dim group 0..3
    const int d0   = g * 128 + lane * 4;
    const int col4 = d0 >> 2;             // float4 column (row = 128 float4)

    // ---- one-time: load 36 coeffs (9 x LDG.128), convert to monomial, pack ----
    float cf[36];
    {
        const float4* c4 = reinterpret_cast<const float4*>(coeff + d0 * NDEG);
        #pragma unroll
        for (int i = 0; i < 9; ++i) {
            float4 v = c4[i];
            cf[4 * i + 0] = v.x; cf[4 * i + 1] = v.y;
            cf[4 * i + 2] = v.z; cf[4 * i + 3] = v.w;
        }
    }
    ull A[9], B[9];
    {
        float t0[9], t1[9];
        cheb2mono(cf + 0,  t0);
        cheb2mono(cf + 9,  t1);
        #pragma unroll
        for (int k = 0; k < 9; ++k) A[k] = pack2(t0[k], t1[k]);
        cheb2mono(cf + 18, t0);
        cheb2mono(cf + 27, t1);
        #pragma unroll
        for (int k = 0; k < 9; ++k) B[k] = pack2(t0[k], t1[k]);
    }

    const int rowbase = blockIdx.x * ROWS_PER_BLOCK;
    const float4* xrow = reinterpret_cast<const float4*>(x);

    // ---- front-batched loads: 8 independent LDG.128 per thread (MLP=8) ----
    float4 xv[ROWS_PER_BLOCK];
    #pragma unroll
    for (int r = 0; r < ROWS_PER_BLOCK; ++r)
        xv[r] = xrow[(size_t)(rowbase + r) * 128 + col4];

    // ---- evaluate all rows ----
    float acc[ROWS_PER_BLOCK];
    #pragma unroll
    for (int r = 0; r < ROWS_PER_BLOCK; ++r)
        acc[r] = eval4(xv[r], A, B);

    // ---- intra-warp reductions (independent chains, latency-overlapped) ----
    #pragma unroll
    for (int off = 16; off; off >>= 1) {
        #pragma unroll
        for (int r = 0; r < ROWS_PER_BLOCK; ++r)
            acc[r] += __shfl_xor_sync(0xffffffffu, acc[r], off);
    }
    if (lane == 0) {
        #pragma unroll
        for (int r = 0; r < ROWS_PER_BLOCK; ++r)
            s_part[r][g] = acc[r];
    }
    __syncthreads();

    // ---- finalize: 8 threads sum the 4 group partials per row ----
    if (tid < ROWS_PER_BLOCK) {
        float4 v = *reinterpret_cast<const float4*>(s_part[tid]);
        out[rowbase + tid] = (v.x + v.y) + (v.z + v.w);
    }
}

extern "C" void kernel_launch(void* const* d_in, const int* in_sizes, int n_in,
                              void* d_out, int out_size)
{
    const float* x     = (const float*)d_in[0];
    const float* coeff = (const float*)d_in[1];
    // d_in[2] = degree (int32, fixed at 8) — baked in at compile time.
    float* out = (float*)d_out;

    kan_cheb_kernel<<<GRID, THREADS>>>(x, coeff, out);
}